// round 12
// baseline (speedup 1.0000x reference)
#include <cuda_runtime.h>
#include <cstdint>

// out[b,s,:] = x[b,s,:] + combined[s,:]  (combined batch-invariant, from 3 PE tables)
// x: [8, 16384, 512] fp32 -> 256 MiB read + 256 MiB write, pure HBM streaming.
// Shape: one block per s-position, 16384 blocks x 64 threads, each thread owns
// 8 contiguous floats (256-bit ld/st, Blackwell v8.f32) — probes DRAM burst
// efficiency, the last untested axis after the 6.0-6.2 TB/s plateau.

#define B_CONST 8
#define D8 64             // D/8 = 512/8
#define MAX_PIXELS 900

struct f8 { float v[8]; };

__device__ __forceinline__ f8 ldg256nc(const float* __restrict__ p) {
    f8 r;
    asm volatile("ld.global.nc.v8.f32 {%0,%1,%2,%3,%4,%5,%6,%7}, [%8];"
                 : "=f"(r.v[0]), "=f"(r.v[1]), "=f"(r.v[2]), "=f"(r.v[3]),
                   "=f"(r.v[4]), "=f"(r.v[5]), "=f"(r.v[6]), "=f"(r.v[7])
                 : "l"(p));
    return r;
}

__device__ __forceinline__ void stg256(float* p, const f8& r) {
    asm volatile("st.global.v8.f32 [%0], {%1,%2,%3,%4,%5,%6,%7,%8};"
                 :: "l"(p),
                    "f"(r.v[0]), "f"(r.v[1]), "f"(r.v[2]), "f"(r.v[3]),
                    "f"(r.v[4]), "f"(r.v[5]), "f"(r.v[6]), "f"(r.v[7])
                 : "memory");
}

__global__ __launch_bounds__(64)
void pe_add_kernel(const float* __restrict__ x,
                   const float* __restrict__ pix_pe,
                   const float* __restrict__ grd_pe,
                   const float* __restrict__ pr_pe,
                   const int*   __restrict__ g_starts,
                   const int*   __restrict__ g_lens,
                   const int*   __restrict__ p_starts,
                   const int*   __restrict__ p_lens,
                   int n_grids, int n_pairs, int n_pairs_pe_rows,
                   int S,
                   float* __restrict__ out)
{
    const int s = blockIdx.x;
    const int t = threadIdx.x;               // 0..63, owns floats [t*8, t*8+8)

    // ---- searchsorted(grid_starts, s, 'right') - 1 ----
    int lo = 0, hi = n_grids;
    while (lo < hi) {
        int mid = (lo + hi) >> 1;
        if (g_starts[mid] <= s) lo = mid + 1; else hi = mid;
    }
    const int gid  = lo - 1;
    const int goff = s - g_starts[gid];
    const bool gmask = (goff < g_lens[gid]);
    int goffc = goff; if (goffc < 0) goffc = 0; if (goffc > MAX_PIXELS - 1) goffc = MAX_PIXELS - 1;

    // ---- searchsorted(pair_starts, s, 'right') - 1 ----
    lo = 0; hi = n_pairs;
    while (lo < hi) {
        int mid = (lo + hi) >> 1;
        if (p_starts[mid] <= s) lo = mid + 1; else hi = mid;
    }
    const int pid  = lo - 1;
    const int poff = s - p_starts[pid];
    const bool pmask = (poff < p_lens[pid]);
    int pidc = pid; if (pidc < 0) pidc = 0; if (pidc > n_pairs_pe_rows - 1) pidc = n_pairs_pe_rows - 1;

    // ---- combined[s, t*8 .. t*8+7] in registers (PE tables L2-resident) ----
    const int dofs = t * 8;
    f8 comb;
#pragma unroll
    for (int i = 0; i < 8; ++i) comb.v[i] = 0.f;
    if (gmask) {
        f8 a = ldg256nc(pix_pe + (size_t)goffc * 512 + dofs);
        f8 g = ldg256nc(grd_pe + (size_t)(gid & 1) * 512 + dofs);
#pragma unroll
        for (int i = 0; i < 8; ++i) comb.v[i] = a.v[i] + g.v[i];
    }
    if (pmask) {
        f8 c = ldg256nc(pr_pe + (size_t)pidc * 512 + dofs);
#pragma unroll
        for (int i = 0; i < 8; ++i) comb.v[i] += c.v[i];
    }

    // ---- per-batch 256-bit load + add + 256-bit store ----
    const size_t row = (size_t)s * 512 + dofs;
    const size_t bstride = (size_t)S * 512;
#pragma unroll
    for (int b = 0; b < B_CONST; ++b) {
        f8 v = ldg256nc(x + row + (size_t)b * bstride);
#pragma unroll
        for (int i = 0; i < 8; ++i) v.v[i] += comb.v[i];
        stg256(out + row + (size_t)b * bstride, v);
    }
}

extern "C" void kernel_launch(void* const* d_in, const int* in_sizes, int n_in,
                              void* d_out, int out_size)
{
    const float* x        = (const float*)d_in[0];
    const float* pix_pe   = (const float*)d_in[1];
    const float* grd_pe   = (const float*)d_in[2];
    const float* pr_pe    = (const float*)d_in[3];
    const int*   g_starts = (const int*)d_in[4];
    const int*   g_lens   = (const int*)d_in[5];
    const int*   p_starts = (const int*)d_in[6];
    const int*   p_lens   = (const int*)d_in[7];

    const int D = in_sizes[2] / 2;            // grids_pe is [2, D]
    const int n_grids = in_sizes[4];
    const int n_pairs = in_sizes[6];
    const int n_pairs_pe_rows = in_sizes[3] / D;
    const int S = out_size / (B_CONST * D);   // 16384

    pe_add_kernel<<<S, 64>>>(
        x, pix_pe, grd_pe, pr_pe,
        g_starts, g_lens, p_starts, p_lens,
        n_grids, n_pairs, n_pairs_pe_rows, S,
        (float*)d_out);
}